// round 2
// baseline (speedup 1.0000x reference)
#include <cuda_runtime.h>

// CIN forward, fused 3 layers, restructured:
//   out[m,s] = sum_f x[m,f] * ( sum_g h[m,g] * W[f*Fk+g, s] )
// -> per-f inner accumulator accf over g (h read straight from smem, packed
//    along m), folded into acc once per f. No p-tile, no per-g barriers.
// W is pre-duplicated into f32x2 form in a __device__ scratch buffer so the
// hot loop has zero pack MOVs: 16 FFMA2 + 2 LDS.128 + 2 LDG.128 per k.
//
// CTA = 64 (b,d) pairs = 4 b's; 8 warps x 8 m; lane = 4 s-columns.

#define F0 39
#define DH 16
#define MTILE 64
#define NT 256
#define K0 (F0 * F0)          // 1521
#define K12 (F0 * 64)         // 2496
#define KTOT (K0 + 2 * K12)   // 6513
#define HS_STRIDE 68          // padded, 16B-aligned rows

__device__ float2 g_wdup[(size_t)KTOT * 128];

__global__ void dup_kernel(const float* __restrict__ W, float2* __restrict__ dst, int n) {
    int i = blockIdx.x * blockDim.x + threadIdx.x;
    if (i < n) { float v = W[i]; dst[i] = make_float2(v, v); }
}

__device__ __forceinline__ void fma2(unsigned long long& d,
                                     unsigned long long a,
                                     unsigned long long b) {
    asm("fma.rn.f32x2 %0, %1, %2, %0;" : "+l"(d) : "l"(a), "l"(b));
}
__device__ __forceinline__ float2 upk(unsigned long long v) {
    float2 r;
    asm("mov.b64 {%0, %1}, %2;" : "=f"(r.x), "=f"(r.y) : "l"(v));
    return r;
}

__global__ __launch_bounds__(NT, 2) void cin_kernel(
    const float* __restrict__ x,
    const float* __restrict__ b0, const float* __restrict__ b1,
    const float* __restrict__ b2,
    float* __restrict__ out)
{
    __shared__ float xs[F0][MTILE];          // [f][m], m contiguous
    __shared__ float hs[64][HS_STRIDE];      // [g][m], m contiguous, padded
    __shared__ float osum[4][256];

    const int tid   = threadIdx.x;
    const int lane  = tid & 31;
    const int w     = tid >> 5;
    const int mbase = w * 8;
    const int s0    = lane * 4;
    const int pair0 = blockIdx.x * MTILE;
    const int b_loc = w >> 1;

    for (int i = tid; i < 4 * 256; i += NT) ((float*)osum)[i] = 0.0f;

    // load x tile transposed: xs[f][m] = x[b, f, d] with pair=pair0+m
    for (int i = tid; i < F0 * MTILE; i += NT) {
        int m = i & (MTILE - 1);
        int f = i >> 6;
        int pair = pair0 + m;
        int b = pair >> 4, d = pair & 15;
        xs[f][m] = x[(size_t)b * (F0 * DH) + f * DH + d];
    }
    __syncthreads();

    const float* bias_ptrs[3] = {b0, b1, b2};
    const size_t koff[3] = {0, (size_t)K0, (size_t)(K0 + K12)};

    for (int layer = 0; layer < 3; ++layer) {
        const int Fk = (layer == 0) ? F0 : 64;
        const float2* __restrict__ wl = g_wdup + koff[layer] * 128;
        const float* hbase = (layer == 0) ? &xs[0][0] : &hs[0][0];
        const int hstride  = (layer == 0) ? MTILE : HS_STRIDE;

        unsigned long long acc[4][4];
        #pragma unroll
        for (int i = 0; i < 4; ++i)
            #pragma unroll
            for (int j = 0; j < 4; ++j) acc[i][j] = 0ull;

        for (int f = 0; f < F0; ++f) {
            unsigned long long accf[4][4];
            #pragma unroll
            for (int i = 0; i < 4; ++i)
                #pragma unroll
                for (int j = 0; j < 4; ++j) accf[i][j] = 0ull;

            const float2* wp = wl + (size_t)f * Fk * 128 + s0;
            const float* hr = hbase + mbase;

            #pragma unroll 4
            for (int g = 0; g < Fk; ++g) {
                ulonglong2 hA = *(const ulonglong2*)(hr);       // m0..m3 pairs
                ulonglong2 hB = *(const ulonglong2*)(hr + 4);   // m4..m7 pairs
                ulonglong2 wA = *(const ulonglong2*)(wp);       // s0,s0+1 dup
                ulonglong2 wB = *(const ulonglong2*)(wp + 2);   // s0+2,s0+3 dup
                fma2(accf[0][0], hA.x, wA.x); fma2(accf[0][1], hA.x, wA.y);
                fma2(accf[0][2], hA.x, wB.x); fma2(accf[0][3], hA.x, wB.y);
                fma2(accf[1][0], hA.y, wA.x); fma2(accf[1][1], hA.y, wA.y);
                fma2(accf[1][2], hA.y, wB.x); fma2(accf[1][3], hA.y, wB.y);
                fma2(accf[2][0], hB.x, wA.x); fma2(accf[2][1], hB.x, wA.y);
                fma2(accf[2][2], hB.x, wB.x); fma2(accf[2][3], hB.x, wB.y);
                fma2(accf[3][0], hB.y, wA.x); fma2(accf[3][1], hB.y, wA.y);
                fma2(accf[3][2], hB.y, wB.x); fma2(accf[3][3], hB.y, wB.y);
                hr += hstride;
                wp += 128;
            }

            // fold: acc[m,s] += x[m,f] * accf[m,s]   (x packed along m)
            const float* xr = &xs[f][mbase];
            ulonglong2 xA = *(const ulonglong2*)(xr);
            ulonglong2 xB = *(const ulonglong2*)(xr + 4);
            #pragma unroll
            for (int sq = 0; sq < 4; ++sq) {
                fma2(acc[0][sq], xA.x, accf[0][sq]);
                fma2(acc[1][sq], xA.y, accf[1][sq]);
                fma2(acc[2][sq], xB.x, accf[2][sq]);
                fma2(acc[3][sq], xB.y, accf[3][sq]);
            }
        }

        // ---- epilogue ----
        const float* bl = bias_ptrs[layer];
        float4 bias4 = __ldg((const float4*)(bl + s0));
        float bias[4] = {bias4.x, bias4.y, bias4.z, bias4.w};
        float sums[4] = {0.f, 0.f, 0.f, 0.f};
        float hv[4][4][2];

        #pragma unroll
        for (int mp = 0; mp < 4; ++mp) {
            #pragma unroll
            for (int sq = 0; sq < 4; ++sq) {
                float2 vv = upk(acc[mp][sq]);
                vv.x = fmaxf(vv.x + bias[sq], 0.0f);
                vv.y = fmaxf(vv.y + bias[sq], 0.0f);
                sums[sq] += vv.x + vv.y;
                hv[mp][sq][0] = vv.x;
                hv[mp][sq][1] = vv.y;
            }
        }

        __syncthreads();   // all reads of hs for this layer complete
        if (layer < 2 && s0 < 64) {
            #pragma unroll
            for (int mp = 0; mp < 4; ++mp)
                #pragma unroll
                for (int sq = 0; sq < 4; ++sq) {
                    hs[s0 + sq][mbase + 2 * mp + 0] = hv[mp][sq][0];
                    hs[s0 + sq][mbase + 2 * mp + 1] = hv[mp][sq][1];
                }
        }

        int ch = -1;
        if (layer == 0)      { if (s0 >= 64) ch = s0 - 64; }   // result 0..63
        else if (layer == 1) { if (s0 >= 64) ch = s0; }        // result 64..127
        else                 { ch = 128 + s0; }                // result 128..255
        if (ch >= 0) {
            #pragma unroll
            for (int sq = 0; sq < 4; ++sq)
                atomicAdd(&osum[b_loc][ch + sq], sums[sq]);
        }
        __syncthreads();   // hs writes visible before next layer reads
    }

    const int bbase = pair0 >> 4;
    for (int i = tid; i < 4 * 256; i += NT) {
        int bl = i >> 8, ch = i & 255;
        out[(size_t)(bbase + bl) * 256 + ch] = osum[bl][ch];
    }
}

extern "C" void kernel_launch(void* const* d_in, const int* in_sizes, int n_in,
                              void* d_out, int out_size) {
    const float* x  = (const float*)d_in[0];
    const float* W0 = (const float*)d_in[1];
    const float* W1 = (const float*)d_in[2];
    const float* W2 = (const float*)d_in[3];
    const float* b0 = (const float*)d_in[4];
    const float* b1 = (const float*)d_in[5];
    const float* b2 = (const float*)d_in[6];
    float* out = (float*)d_out;

    float2* wdup;
    cudaGetSymbolAddress((void**)&wdup, g_wdup);

    const int n0 = K0 * 128, n12 = K12 * 128;
    dup_kernel<<<(n0 + 255) / 256, 256>>>(W0, wdup, n0);
    dup_kernel<<<(n12 + 255) / 256, 256>>>(W1, wdup + (size_t)K0 * 128, n12);
    dup_kernel<<<(n12 + 255) / 256, 256>>>(W2, wdup + (size_t)(K0 + K12) * 128, n12);

    const int pairs = 2048 * 16;
    cin_kernel<<<pairs / MTILE, NT>>>(x, b0, b1, b2, out);
}

// round 3
// speedup vs baseline: 1.0001x; 1.0001x over previous
#include <cuda_runtime.h>

// CIN forward, fused 3 layers, restructured:
//   out[m,s] = sum_f x[m,f] * ( sum_g h[m,g] * W[f*Fk+g, s] )
// -> per-f inner accumulator accf over g (h read straight from smem, packed
//    along m), folded into acc once per f. No p-tile, no per-g barriers.
// W is pre-duplicated into f32x2 form in a __device__ scratch buffer so the
// hot loop has zero pack MOVs: 16 FFMA2 + 2 LDS.128 + 2 LDG.128 per k.
//
// CTA = 64 (b,d) pairs = 4 b's; 8 warps x 8 m; lane = 4 s-columns.

#define F0 39
#define DH 16
#define MTILE 64
#define NT 256
#define K0 (F0 * F0)          // 1521
#define K12 (F0 * 64)         // 2496
#define KTOT (K0 + 2 * K12)   // 6513
#define HS_STRIDE 68          // padded, 16B-aligned rows

__device__ float2 g_wdup[(size_t)KTOT * 128];

__global__ void dup_kernel(const float* __restrict__ W, float2* __restrict__ dst, int n) {
    int i = blockIdx.x * blockDim.x + threadIdx.x;
    if (i < n) { float v = W[i]; dst[i] = make_float2(v, v); }
}

__device__ __forceinline__ void fma2(unsigned long long& d,
                                     unsigned long long a,
                                     unsigned long long b) {
    asm("fma.rn.f32x2 %0, %1, %2, %0;" : "+l"(d) : "l"(a), "l"(b));
}
__device__ __forceinline__ float2 upk(unsigned long long v) {
    float2 r;
    asm("mov.b64 {%0, %1}, %2;" : "=f"(r.x), "=f"(r.y) : "l"(v));
    return r;
}

__global__ __launch_bounds__(NT, 2) void cin_kernel(
    const float* __restrict__ x,
    const float* __restrict__ b0, const float* __restrict__ b1,
    const float* __restrict__ b2,
    float* __restrict__ out)
{
    __shared__ float xs[F0][MTILE];          // [f][m], m contiguous
    __shared__ float hs[64][HS_STRIDE];      // [g][m], m contiguous, padded
    __shared__ float osum[4][256];

    const int tid   = threadIdx.x;
    const int lane  = tid & 31;
    const int w     = tid >> 5;
    const int mbase = w * 8;
    const int s0    = lane * 4;
    const int pair0 = blockIdx.x * MTILE;
    const int b_loc = w >> 1;

    for (int i = tid; i < 4 * 256; i += NT) ((float*)osum)[i] = 0.0f;

    // load x tile transposed: xs[f][m] = x[b, f, d] with pair=pair0+m
    for (int i = tid; i < F0 * MTILE; i += NT) {
        int m = i & (MTILE - 1);
        int f = i >> 6;
        int pair = pair0 + m;
        int b = pair >> 4, d = pair & 15;
        xs[f][m] = x[(size_t)b * (F0 * DH) + f * DH + d];
    }
    __syncthreads();

    const float* bias_ptrs[3] = {b0, b1, b2};
    const size_t koff[3] = {0, (size_t)K0, (size_t)(K0 + K12)};

    for (int layer = 0; layer < 3; ++layer) {
        const int Fk = (layer == 0) ? F0 : 64;
        const float2* __restrict__ wl = g_wdup + koff[layer] * 128;
        const float* hbase = (layer == 0) ? &xs[0][0] : &hs[0][0];
        const int hstride  = (layer == 0) ? MTILE : HS_STRIDE;

        unsigned long long acc[4][4];
        #pragma unroll
        for (int i = 0; i < 4; ++i)
            #pragma unroll
            for (int j = 0; j < 4; ++j) acc[i][j] = 0ull;

        for (int f = 0; f < F0; ++f) {
            unsigned long long accf[4][4];
            #pragma unroll
            for (int i = 0; i < 4; ++i)
                #pragma unroll
                for (int j = 0; j < 4; ++j) accf[i][j] = 0ull;

            const float2* wp = wl + (size_t)f * Fk * 128 + s0;
            const float* hr = hbase + mbase;

            #pragma unroll 4
            for (int g = 0; g < Fk; ++g) {
                ulonglong2 hA = *(const ulonglong2*)(hr);       // m0..m3 pairs
                ulonglong2 hB = *(const ulonglong2*)(hr + 4);   // m4..m7 pairs
                ulonglong2 wA = *(const ulonglong2*)(wp);       // s0,s0+1 dup
                ulonglong2 wB = *(const ulonglong2*)(wp + 2);   // s0+2,s0+3 dup
                fma2(accf[0][0], hA.x, wA.x); fma2(accf[0][1], hA.x, wA.y);
                fma2(accf[0][2], hA.x, wB.x); fma2(accf[0][3], hA.x, wB.y);
                fma2(accf[1][0], hA.y, wA.x); fma2(accf[1][1], hA.y, wA.y);
                fma2(accf[1][2], hA.y, wB.x); fma2(accf[1][3], hA.y, wB.y);
                fma2(accf[2][0], hB.x, wA.x); fma2(accf[2][1], hB.x, wA.y);
                fma2(accf[2][2], hB.x, wB.x); fma2(accf[2][3], hB.x, wB.y);
                fma2(accf[3][0], hB.y, wA.x); fma2(accf[3][1], hB.y, wA.y);
                fma2(accf[3][2], hB.y, wB.x); fma2(accf[3][3], hB.y, wB.y);
                hr += hstride;
                wp += 128;
            }

            // fold: acc[m,s] += x[m,f] * accf[m,s]   (x packed along m)
            const float* xr = &xs[f][mbase];
            ulonglong2 xA = *(const ulonglong2*)(xr);
            ulonglong2 xB = *(const ulonglong2*)(xr + 4);
            #pragma unroll
            for (int sq = 0; sq < 4; ++sq) {
                fma2(acc[0][sq], xA.x, accf[0][sq]);
                fma2(acc[1][sq], xA.y, accf[1][sq]);
                fma2(acc[2][sq], xB.x, accf[2][sq]);
                fma2(acc[3][sq], xB.y, accf[3][sq]);
            }
        }

        // ---- epilogue ----
        const float* bl = bias_ptrs[layer];
        float4 bias4 = __ldg((const float4*)(bl + s0));
        float bias[4] = {bias4.x, bias4.y, bias4.z, bias4.w};
        float sums[4] = {0.f, 0.f, 0.f, 0.f};
        float hv[4][4][2];

        #pragma unroll
        for (int mp = 0; mp < 4; ++mp) {
            #pragma unroll
            for (int sq = 0; sq < 4; ++sq) {
                float2 vv = upk(acc[mp][sq]);
                vv.x = fmaxf(vv.x + bias[sq], 0.0f);
                vv.y = fmaxf(vv.y + bias[sq], 0.0f);
                sums[sq] += vv.x + vv.y;
                hv[mp][sq][0] = vv.x;
                hv[mp][sq][1] = vv.y;
            }
        }

        __syncthreads();   // all reads of hs for this layer complete
        if (layer < 2 && s0 < 64) {
            #pragma unroll
            for (int mp = 0; mp < 4; ++mp)
                #pragma unroll
                for (int sq = 0; sq < 4; ++sq) {
                    hs[s0 + sq][mbase + 2 * mp + 0] = hv[mp][sq][0];
                    hs[s0 + sq][mbase + 2 * mp + 1] = hv[mp][sq][1];
                }
        }

        int ch = -1;
        if (layer == 0)      { if (s0 >= 64) ch = s0 - 64; }   // result 0..63
        else if (layer == 1) { if (s0 >= 64) ch = s0; }        // result 64..127
        else                 { ch = 128 + s0; }                // result 128..255
        if (ch >= 0) {
            #pragma unroll
            for (int sq = 0; sq < 4; ++sq)
                atomicAdd(&osum[b_loc][ch + sq], sums[sq]);
        }
        __syncthreads();   // hs writes visible before next layer reads
    }

    const int bbase = pair0 >> 4;
    for (int i = tid; i < 4 * 256; i += NT) {
        int bl = i >> 8, ch = i & 255;
        out[(size_t)(bbase + bl) * 256 + ch] = osum[bl][ch];
    }
}

extern "C" void kernel_launch(void* const* d_in, const int* in_sizes, int n_in,
                              void* d_out, int out_size) {
    const float* x  = (const float*)d_in[0];
    const float* W0 = (const float*)d_in[1];
    const float* W1 = (const float*)d_in[2];
    const float* W2 = (const float*)d_in[3];
    const float* b0 = (const float*)d_in[4];
    const float* b1 = (const float*)d_in[5];
    const float* b2 = (const float*)d_in[6];
    float* out = (float*)d_out;

    float2* wdup;
    cudaGetSymbolAddress((void**)&wdup, g_wdup);

    const int n0 = K0 * 128, n12 = K12 * 128;
    dup_kernel<<<(n0 + 255) / 256, 256>>>(W0, wdup, n0);
    dup_kernel<<<(n12 + 255) / 256, 256>>>(W1, wdup + (size_t)K0 * 128, n12);
    dup_kernel<<<(n12 + 255) / 256, 256>>>(W2, wdup + (size_t)(K0 + K12) * 128, n12);

    const int pairs = 2048 * 16;
    cin_kernel<<<pairs / MTILE, NT>>>(x, b0, b1, b2, out);
}

// round 5
// speedup vs baseline: 4.1986x; 4.1981x over previous
#include <cuda_runtime.h>
#include <cstdint>

// CIN forward via warp-level TF32 mma.sync (m16n8k8), 3 fused GEMM layers.
// CTA = 128 m-rows (8 b's) x 128 n. 8 warps = 2m x 4n, each 64x32.
// A (=x[m,f]*h[m,g]) and B (pre-gathered W) staged in smem in FRAGMENT ORDER.

#define NCH0 48
#define NCH12 78
#define NCHT 204

__device__ __align__(16) float g_wt[(size_t)NCHT * 4096];  // per-chunk B fragments

#define SM_OSUM 0        // 8*256 floats = 8192 B
#define SM_BIAS 8192     // 384 floats   = 1536 B
#define SM_XS   9728     // 128*41*4     = 20992 B
#define SM_HS   30720    // 128*65*4     = 33280 B
#define SM_A    64000    // 16384 B (A frags, [kstep][mtile][lane][4])
#define SM_B    80384    // 16384 B (B frags, [kstep][ntile][lane][2])
#define SM_TOT  96768

__device__ __forceinline__ float tf32r(float v) {
    uint32_t r; asm("cvt.rna.tf32.f32 %0, %1;" : "=r"(r) : "f"(v));
    return __uint_as_float(r);
}
__device__ __forceinline__ void mma8(float* c, const uint32_t* a, const uint32_t* b) {
    asm volatile("mma.sync.aligned.m16n8k8.row.col.f32.tf32.tf32.f32 "
        "{%0,%1,%2,%3}, {%4,%5,%6,%7}, {%8,%9}, {%0,%1,%2,%3};"
        : "+f"(c[0]), "+f"(c[1]), "+f"(c[2]), "+f"(c[3])
        : "r"(a[0]), "r"(a[1]), "r"(a[2]), "r"(a[3]), "r"(b[0]), "r"(b[1]));
}

// Gather W[k,n] (tf32-rounded) into per-chunk fragment order:
// flat rem = ((kstep*16 + ntile)*32 + lane)*2 + reg ; n = ntile*8 + lane/4,
// k = chunk*32 + kstep*8 + lane%4 + reg*4.  (B col-major frag for m16n8k8)
__global__ void wt_prep(const float* __restrict__ W, int K, int chunk0, int nchunks) {
    int idx = blockIdx.x * 256 + threadIdx.x;
    if (idx >= nchunks * 4096) return;
    int cl = idx >> 12, rem = idx & 4095;
    int lane = (rem >> 1) & 31, reg = rem & 1;
    int n = ((rem >> 6) & 15) * 8 + (lane >> 2);
    int k = cl * 32 + (rem >> 10) * 8 + (lane & 3) + reg * 4;
    float v = (k < K) ? W[(size_t)k * 128 + n] : 0.0f;
    g_wt[(size_t)(chunk0 + cl) * 4096 + rem] = tf32r(v);
}

__global__ void __launch_bounds__(256) cin_mma_kernel(
    const float* __restrict__ x,
    const float* __restrict__ b0, const float* __restrict__ b1,
    const float* __restrict__ b2,
    float* __restrict__ out)
{
    extern __shared__ char smem[];
    float* osum   = (float*)(smem + SM_OSUM);
    float* bias_s = (float*)(smem + SM_BIAS);
    float* xs     = (float*)(smem + SM_XS);   // [m][41]
    float* hs     = (float*)(smem + SM_HS);   // [m][65]

    const int tid = threadIdx.x, lane = tid & 31, wid = tid >> 5;
    const int pair0 = blockIdx.x * 128;

    for (int i = tid; i < 2048; i += 256) osum[i] = 0.0f;
    for (int i = tid; i < 128 * 39; i += 256) {
        int m = i & 127, f = i >> 7, pr = pair0 + m;
        xs[m * 41 + f] = x[((size_t)(pr >> 4) * 39 + f) * 16 + (pr & 15)];
    }
    for (int i = tid; i < 384; i += 256) {
        const float* bp = (i < 128) ? b0 : ((i < 256) ? b1 : b2);
        bias_s[i] = bp[i & 127];
    }

    float acc[4][4][4];
    #pragma unroll
    for (int a = 0; a < 4; ++a)
        #pragma unroll
        for (int b = 0; b < 4; ++b)
            #pragma unroll
            for (int c = 0; c < 4; ++c) acc[a][b][c] = 0.0f;

    int gchunk = 0;
    const int wm = wid & 1, wn = wid >> 1;      // warp m-half, n-quarter

    for (int layer = 0; layer < 3; ++layer) {
        const int nck = (layer == 0) ? NCH0 : NCH12;
        const float* hb = (layer == 0) ? xs : hs;
        const int hst = (layer == 0) ? 41 : 65;

        for (int ic = 0; ic < nck; ++ic) {
            __syncthreads();   // previous chunk's frag LDS done; xs/hs ready

            // ---- B copy: contiguous, fragment order preserved ----
            {
                const float4* bsrc = (const float4*)(g_wt + (size_t)gchunk * 4096);
                float4* bdst = (float4*)(smem + SM_B);
                #pragma unroll
                for (int j = 0; j < 4; ++j) bdst[tid + 256 * j] = bsrc[tid + 256 * j];
            }
            // ---- A fill in fragment order: slot -> (kstep, mtile, lane') ----
            {
                float4* adst = (float4*)(smem + SM_A);
                #pragma unroll
                for (int j = 0; j < 4; ++j) {
                    int slot = tid + 256 * j;
                    int l2 = slot & 31, mt_ks = slot >> 5;
                    int mtile = mt_ks & 7, kstep = mt_ks >> 3;
                    int r = l2 >> 2, c = l2 & 3;
                    int m = mtile * 16 + r;
                    int k = ic * 32 + kstep * 8 + c;       // layer-local k (k and k+4)
                    int f0, g0, f1, g1;
                    bool ok0 = true, ok1 = true;
                    if (layer == 0) {
                        unsigned ku = (unsigned)k;
                        f0 = (int)((ku * 13444u) >> 19); g0 = k - f0 * 39;
                        unsigned k2 = ku + 4u;
                        f1 = (int)((k2 * 13444u) >> 19); g1 = (int)k2 - f1 * 39;
                        ok0 = (k < 1521); ok1 = (k + 4 < 1521);
                        if (!ok0) { f0 = 0; g0 = 0; }
                        if (!ok1) { f1 = 0; g1 = 0; }
                    } else {
                        f0 = k >> 6; g0 = k & 63;
                        f1 = (k + 4) >> 6; g1 = (k + 4) & 63;
                    }
                    float xa = xs[m * 41 + f0],       xb = xs[(m + 8) * 41 + f0];
                    float ha = hb[m * hst + g0],      hbv = hb[(m + 8) * hst + g0];
                    float xc = xs[m * 41 + f1],       xd = xs[(m + 8) * 41 + f1];
                    float hc = hb[m * hst + g1],      hd = hb[(m + 8) * hst + g1];
                    float4 o;
                    o.x = ok0 ? tf32r(xa * ha)  : 0.0f;   // (r,   c)
                    o.y = ok0 ? tf32r(xb * hbv) : 0.0f;   // (r+8, c)
                    o.z = ok1 ? tf32r(xc * hc)  : 0.0f;   // (r,   c+4)
                    o.w = ok1 ? tf32r(xd * hd)  : 0.0f;   // (r+8, c+4)
                    adst[slot] = o;
                }
            }
            __syncthreads();

            // ---- MMA phase: frag loads are single LDS.128 / LDS.64 ----
            const uint4* A4 = (const uint4*)(smem + SM_A);
            const uint2* B2 = (const uint2*)(smem + SM_B);
            #pragma unroll
            for (int ks = 0; ks < 4; ++ks) {
                uint32_t afr[4][4], bfr[4][2];
                #pragma unroll
                for (int mt = 0; mt < 4; ++mt) {
                    uint4 av = A4[(ks * 8 + wm * 4 + mt) * 32 + lane];
                    afr[mt][0] = av.x; afr[mt][1] = av.y; afr[mt][2] = av.z; afr[mt][3] = av.w;
                }
                #pragma unroll
                for (int nt = 0; nt < 4; ++nt) {
                    uint2 bv = B2[(ks * 16 + wn * 4 + nt) * 32 + lane];
                    bfr[nt][0] = bv.x; bfr[nt][1] = bv.y;
                }
                #pragma unroll
                for (int mt = 0; mt < 4; ++mt)
                    #pragma unroll
                    for (int nt = 0; nt < 4; ++nt)
                        mma8(acc[mt][nt], afr[mt], bfr[nt]);
            }
            ++gchunk;
        }

        // ---- epilogue: bias + relu, h for next layer, d-sum into osum ----
        #pragma unroll
        for (int mt = 0; mt < 4; ++mt) {
            int b_loc = wm * 4 + mt;
            int m = wm * 64 + mt * 16 + (lane >> 2);
            #pragma unroll
            for (int nt = 0; nt < 4; ++nt) {
                int n = wn * 32 + nt * 8 + (lane & 3) * 2;
                float bi0 = bias_s[layer * 128 + n];
                float bi1 = bias_s[layer * 128 + n + 1];
                float v0 = fmaxf(acc[mt][nt][0] + bi0, 0.0f);
                float v1 = fmaxf(acc[mt][nt][1] + bi1, 0.0f);
                float v2 = fmaxf(acc[mt][nt][2] + bi0, 0.0f);
                float v3 = fmaxf(acc[mt][nt][3] + bi1, 0.0f);
                acc[mt][nt][0] = 0.0f; acc[mt][nt][1] = 0.0f;
                acc[mt][nt][2] = 0.0f; acc[mt][nt][3] = 0.0f;
                if (layer < 2 && n < 64) {
                    hs[m * 65 + n] = v0;       hs[m * 65 + n + 1] = v1;
                    hs[(m + 8) * 65 + n] = v2; hs[(m + 8) * 65 + n + 1] = v3;
                }
                int ch = (layer == 0) ? (n >= 64 ? n - 64 : -1)
                       : (layer == 1) ? (n >= 64 ? n : -1)
                       : (128 + n);
                if (ch >= 0) {
                    atomicAdd(&osum[b_loc * 256 + ch],     v0 + v2);
                    atomicAdd(&osum[b_loc * 256 + ch + 1], v1 + v3);
                }
            }
        }
        __syncthreads();   // hs/osum visible before next layer / output
    }

    const int bbase = blockIdx.x * 8;
    for (int i = tid; i < 2048; i += 256)
        out[(size_t)(bbase + (i >> 8)) * 256 + (i & 255)] = osum[i];
}

extern "C" void kernel_launch(void* const* d_in, const int* in_sizes, int n_in,
                              void* d_out, int out_size) {
    const float* x  = (const float*)d_in[0];
    const float* W0 = (const float*)d_in[1];
    const float* W1 = (const float*)d_in[2];
    const float* W2 = (const float*)d_in[3];
    const float* b0 = (const float*)d_in[4];
    const float* b1 = (const float*)d_in[5];
    const float* b2 = (const float*)d_in[6];
    float* out = (float*)d_out;

    wt_prep<<<NCH0  * 16, 256>>>(W0, 1521, 0, NCH0);
    wt_prep<<<NCH12 * 16, 256>>>(W1, 2496, NCH0, NCH12);
    wt_prep<<<NCH12 * 16, 256>>>(W2, 2496, NCH0 + NCH12, NCH12);

    cudaFuncSetAttribute(cin_mma_kernel, cudaFuncAttributeMaxDynamicSharedMemorySize, SM_TOT);
    cin_mma_kernel<<<256, 256, SM_TOT>>>(x, b0, b1, b2, out);
}

// round 6
// speedup vs baseline: 4.9096x; 1.1693x over previous
#include <cuda_runtime.h>
#include <cstdint>

// CIN forward via warp-level TF32 mma.sync (m16n8k8), 3 fused GEMM layers.
// CTA = 128m x 128n, 8 warps = 2m x 4n. A double-buffered in smem (fragment
// order); B read directly from L2-resident g_wt (uint4 fragment order) via
// LDG.128. One __syncthreads per K-chunk: sync; MMA(i); fill(i+1).

#define NCH0 48
#define NCH12 78
#define NCHT 204

__device__ __align__(16) float g_wt[(size_t)NCHT * 4096];  // per-chunk B frags (uint4 order)

#define SM_OSUM 0        // 8*256 floats
#define SM_BIAS 8192     // 384 floats
#define SM_XS   9728     // 128*41*4
#define SM_HS   30720    // 128*65*4
#define SM_A0   64000    // 16 KB A frag buffer 0
#define SM_A1   80384    // 16 KB A frag buffer 1
#define SM_TOT  96768

__device__ __forceinline__ float tf32r(float v) {
    uint32_t r; asm("cvt.rna.tf32.f32 %0, %1;" : "=r"(r) : "f"(v));
    return __uint_as_float(r);
}
__device__ __forceinline__ void mma8(float* c, const uint32_t* a, uint32_t b0, uint32_t b1) {
    asm volatile("mma.sync.aligned.m16n8k8.row.col.f32.tf32.tf32.f32 "
        "{%0,%1,%2,%3}, {%4,%5,%6,%7}, {%8,%9}, {%0,%1,%2,%3};"
        : "+f"(c[0]), "+f"(c[1]), "+f"(c[2]), "+f"(c[3])
        : "r"(a[0]), "r"(a[1]), "r"(a[2]), "r"(a[3]), "r"(b0), "r"(b1));
}

// B gather, uint4-per-lane order:
//   rem = ((kp*16 + ntile)*32 + lane)*4 + r,  r = (ks&1)*2 + reg, ks = kp*2+(r>>1)
//   n = ntile*8 + lane/4 ; k = chunk*32 + ks*8 + lane%4 + reg*4
__global__ void wt_prep(const float* __restrict__ W, int K, int chunk0, int nchunks) {
    int idx = blockIdx.x * 256 + threadIdx.x;
    if (idx >= nchunks * 4096) return;
    int cl = idx >> 12, rem = idx & 4095;
    int r = rem & 3, lane = (rem >> 2) & 31, ntile = (rem >> 7) & 15, kp = rem >> 11;
    int ks = kp * 2 + (r >> 1), reg = r & 1;
    int n = ntile * 8 + (lane >> 2);
    int k = cl * 32 + ks * 8 + (lane & 3) + reg * 4;
    float v = (k < K) ? W[(size_t)k * 128 + n] : 0.0f;
    g_wt[(size_t)(chunk0 + cl) * 4096 + rem] = tf32r(v);
}

// A-fill for one 32-wide K chunk into fragment-order buffer `adst`.
__device__ __forceinline__ void fill_A(float4* adst, const float* __restrict__ xs,
                                       const float* __restrict__ hb, int hst,
                                       int layer, int ic, int tid) {
    #pragma unroll
    for (int j = 0; j < 4; ++j) {
        int slot = tid + 256 * j;
        int l2 = slot & 31, mt_ks = slot >> 5;
        int mtile = mt_ks & 7, kstep = mt_ks >> 3;
        int r = l2 >> 2, c = l2 & 3;
        int m = mtile * 16 + r;
        int k = ic * 32 + kstep * 8 + c;
        int f0, g0, f1, g1;
        bool ok0 = true, ok1 = true;
        if (layer == 0) {
            unsigned ku = (unsigned)k;
            f0 = (int)((ku * 13444u) >> 19); g0 = k - f0 * 39;
            unsigned k2 = ku + 4u;
            f1 = (int)((k2 * 13444u) >> 19); g1 = (int)k2 - f1 * 39;
            ok0 = (k < 1521); ok1 = (k + 4 < 1521);
            if (!ok0) { f0 = 0; g0 = 0; }
            if (!ok1) { f1 = 0; g1 = 0; }
        } else {
            f0 = k >> 6; g0 = k & 63;
            f1 = (k + 4) >> 6; g1 = (k + 4) & 63;
        }
        float xa = xs[m * 41 + f0],  xb = xs[(m + 8) * 41 + f0];
        float ha = hb[m * hst + g0], hv = hb[(m + 8) * hst + g0];
        float xc = xs[m * 41 + f1],  xd = xs[(m + 8) * 41 + f1];
        float hc = hb[m * hst + g1], hd = hb[(m + 8) * hst + g1];
        float4 o;
        o.x = ok0 ? tf32r(xa * ha) : 0.0f;
        o.y = ok0 ? tf32r(xb * hv) : 0.0f;
        o.z = ok1 ? tf32r(xc * hc) : 0.0f;
        o.w = ok1 ? tf32r(xd * hd) : 0.0f;
        adst[slot] = o;
    }
}

__global__ void __launch_bounds__(256, 2) cin_mma_kernel(
    const float* __restrict__ x,
    const float* __restrict__ b0, const float* __restrict__ b1,
    const float* __restrict__ b2,
    float* __restrict__ out)
{
    extern __shared__ char smem[];
    float* osum   = (float*)(smem + SM_OSUM);
    float* bias_s = (float*)(smem + SM_BIAS);
    float* xs     = (float*)(smem + SM_XS);   // [m][41]
    float* hs     = (float*)(smem + SM_HS);   // [m][65]
    float4* abuf[2] = {(float4*)(smem + SM_A0), (float4*)(smem + SM_A1)};

    const int tid = threadIdx.x, lane = tid & 31, wid = tid >> 5;
    const int pair0 = blockIdx.x * 128;
    const int wm = wid & 1, wn = wid >> 1;

    for (int i = tid; i < 2048; i += 256) osum[i] = 0.0f;
    for (int i = tid; i < 128 * 39; i += 256) {
        int m = i & 127, f = i >> 7, pr = pair0 + m;
        xs[m * 41 + f] = x[((size_t)(pr >> 4) * 39 + f) * 16 + (pr & 15)];
    }
    for (int i = tid; i < 384; i += 256) {
        const float* bp = (i < 128) ? b0 : ((i < 256) ? b1 : b2);
        bias_s[i] = bp[i & 127];
    }

    float acc[4][4][4];
    #pragma unroll
    for (int a = 0; a < 4; ++a)
        #pragma unroll
        for (int b = 0; b < 4; ++b)
            #pragma unroll
            for (int c = 0; c < 4; ++c) acc[a][b][c] = 0.0f;

    int gchunk = 0;
    int pb = 0;

    for (int layer = 0; layer < 3; ++layer) {
        const int nck = (layer == 0) ? NCH0 : NCH12;
        const float* hb = (layer == 0) ? xs : hs;
        const int hst = (layer == 0) ? 41 : 65;

        __syncthreads();                       // xs/hs (epilogue writes) visible
        fill_A(abuf[pb], xs, hb, hst, layer, 0, tid);

        for (int ic = 0; ic < nck; ++ic) {
            __syncthreads();                   // fill(ic) visible; prior reads of abuf[pb^1] done

            // ---- MMA(ic): A from abuf[pb], B straight from L2 ----
            const uint4* A4 = (const uint4*)abuf[pb];
            const uint4* bsrc = (const uint4*)(g_wt + (size_t)gchunk * 4096);
            #pragma unroll
            for (int kp = 0; kp < 2; ++kp) {
                uint4 bfr[4];
                #pragma unroll
                for (int nt = 0; nt < 4; ++nt)
                    bfr[nt] = bsrc[(kp * 16 + wn * 4 + nt) * 32 + lane];
                #pragma unroll
                for (int k2 = 0; k2 < 2; ++k2) {
                    int ks = kp * 2 + k2;
                    uint32_t afr[4][4];
                    #pragma unroll
                    for (int mt = 0; mt < 4; ++mt) {
                        uint4 av = A4[(ks * 8 + wm * 4 + mt) * 32 + lane];
                        afr[mt][0] = av.x; afr[mt][1] = av.y;
                        afr[mt][2] = av.z; afr[mt][3] = av.w;
                    }
                    #pragma unroll
                    for (int mt = 0; mt < 4; ++mt)
                        #pragma unroll
                        for (int nt = 0; nt < 4; ++nt)
                            mma8(acc[mt][nt], afr[mt],
                                 k2 ? bfr[nt].z : bfr[nt].x,
                                 k2 ? bfr[nt].w : bfr[nt].y);
                }
            }

            // ---- fill(ic+1) into the other buffer ----
            if (ic + 1 < nck)
                fill_A(abuf[pb ^ 1], xs, hb, hst, layer, ic + 1, tid);
            pb ^= 1;
            ++gchunk;
        }

        // ---- epilogue: bias + relu, h for next layer, d-sum ----
        #pragma unroll
        for (int mt = 0; mt < 4; ++mt) {
            int b_loc = wm * 4 + mt;
            int m = wm * 64 + mt * 16 + (lane >> 2);
            #pragma unroll
            for (int nt = 0; nt < 4; ++nt) {
                int n = wn * 32 + nt * 8 + (lane & 3) * 2;
                float bi0 = bias_s[layer * 128 + n];
                float bi1 = bias_s[layer * 128 + n + 1];
                float v0 = fmaxf(acc[mt][nt][0] + bi0, 0.0f);
                float v1 = fmaxf(acc[mt][nt][1] + bi1, 0.0f);
                float v2 = fmaxf(acc[mt][nt][2] + bi0, 0.0f);
                float v3 = fmaxf(acc[mt][nt][3] + bi1, 0.0f);
                acc[mt][nt][0] = 0.0f; acc[mt][nt][1] = 0.0f;
                acc[mt][nt][2] = 0.0f; acc[mt][nt][3] = 0.0f;
                if (layer < 2 && n < 64) {
                    hs[m * 65 + n] = v0;       hs[m * 65 + n + 1] = v1;
                    hs[(m + 8) * 65 + n] = v2; hs[(m + 8) * 65 + n + 1] = v3;
                }
                int ch = (layer == 0) ? (n >= 64 ? n - 64 : -1)
                       : (layer == 1) ? (n >= 64 ? n : -1)
                       : (128 + n);
                if (ch >= 0) {
                    atomicAdd(&osum[b_loc * 256 + ch],     v0 + v2);
                    atomicAdd(&osum[b_loc * 256 + ch + 1], v1 + v3);
                }
            }
        }
    }

    __syncthreads();
    const int bbase = blockIdx.x * 8;
    for (int i = tid; i < 2048; i += 256)
        out[(size_t)(bbase + (i >> 8)) * 256 + (i & 255)] = osum[i];
}

extern "C" void kernel_launch(void* const* d_in, const int* in_sizes, int n_in,
                              void* d_out, int out_size) {
    const float* x  = (const float*)d_in[0];
    const float* W0 = (const float*)d_in[1];
    const float* W1 = (const float*)d_in[2];
    const float* W2 = (const float*)d_in[3];
    const float* b0 = (const float*)d_in[4];
    const float* b1 = (const float*)d_in[5];
    const float* b2 = (const float*)d_in[6];
    float* out = (float*)d_out;

    wt_prep<<<NCH0  * 16, 256>>>(W0, 1521, 0, NCH0);
    wt_prep<<<NCH12 * 16, 256>>>(W1, 2496, NCH0, NCH12);
    wt_prep<<<NCH12 * 16, 256>>>(W2, 2496, NCH0 + NCH12, NCH12);

    cudaFuncSetAttribute(cin_mma_kernel, cudaFuncAttributeMaxDynamicSharedMemorySize, SM_TOT);
    cin_mma_kernel<<<256, 256, SM_TOT>>>(x, b0, b1, b2, out);
}

// round 7
// speedup vs baseline: 5.8784x; 1.1973x over previous
#include <cuda_runtime.h>
#include <cstdint>

// CIN forward via warp-level TF32 mma.sync (m16n8k8), 3 fused GEMM layers.
// Layer 0 folded symmetric (h=x): K0 = 780 (pad 800). B fragments kept in
// registers and prefetched one chunk ahead (LDG latency hidden under fill).
// CTA = 128m x 128n, 8 warps = 2m x 4n. A double-buffered in smem.

#define NCH0 25
#define NCH12 78
#define NCHT 181

__device__ __align__(16) float g_wt[(size_t)(NCHT + 1) * 4096];  // +1 pad chunk for prefetch

#define SM_OSUM 0        // 2048 f
#define SM_BIAS 8192     // 384 f
#define SM_LUT  9728     // 800 u32
#define SM_XS   12928    // 128*41*4
#define SM_HS   33920    // 128*65*4
#define SM_A0   67200    // 16 KB
#define SM_A1   83584    // 16 KB
#define SM_TOT  99968

__device__ __forceinline__ float tf32r(float v) {
    uint32_t r; asm("cvt.rna.tf32.f32 %0, %1;" : "=r"(r) : "f"(v));
    return __uint_as_float(r);
}
__device__ __forceinline__ void mma8(float* c, const uint32_t* a, uint32_t b0, uint32_t b1) {
    asm volatile("mma.sync.aligned.m16n8k8.row.col.f32.tf32.tf32.f32 "
        "{%0,%1,%2,%3}, {%4,%5,%6,%7}, {%8,%9}, {%0,%1,%2,%3};"
        : "+f"(c[0]), "+f"(c[1]), "+f"(c[2]), "+f"(c[3])
        : "r"(a[0]), "r"(a[1]), "r"(a[2]), "r"(a[3]), "r"(b0), "r"(b1));
}

// ---- W prep: fragment order rem = ((kp*16+ntile)*32+lane)*4 + r ----
// ks = kp*2 + (r>>1), reg = r&1 ; n = ntile*8 + lane/4 ; k = cl*32 + ks*8 + lane%4 + reg*4
__global__ void wt_prep0(const float* __restrict__ W) {   // layer 0, symmetric fold
    int idx = blockIdx.x * 256 + threadIdx.x;
    if (idx >= NCH0 * 4096) return;
    int cl = idx >> 12, rem = idx & 4095;
    int r = rem & 3, lane = (rem >> 2) & 31, ntile = (rem >> 7) & 15, kp = rem >> 11;
    int ks = kp * 2 + (r >> 1), reg = r & 1;
    int n = ntile * 8 + (lane >> 2);
    int k = cl * 32 + ks * 8 + (lane & 3) + reg * 4;
    float v = 0.0f;
    if (k < 780) {
        int f = 0, s = 0;
        while (s + (39 - f) <= k) { s += 39 - f; ++f; }
        int g = f + (k - s);
        v = W[(size_t)(f * 39 + g) * 128 + n];
        if (g != f) v += W[(size_t)(g * 39 + f) * 128 + n];
    }
    g_wt[(size_t)cl * 4096 + rem] = tf32r(v);
}
__global__ void wt_prep(const float* __restrict__ W, int K, int chunk0, int nchunks) {
    int idx = blockIdx.x * 256 + threadIdx.x;
    if (idx >= nchunks * 4096) return;
    int cl = idx >> 12, rem = idx & 4095;
    int r = rem & 3, lane = (rem >> 2) & 31, ntile = (rem >> 7) & 15, kp = rem >> 11;
    int ks = kp * 2 + (r >> 1), reg = r & 1;
    int n = ntile * 8 + (lane >> 2);
    int k = cl * 32 + ks * 8 + (lane & 3) + reg * 4;
    float v = (k < K) ? W[(size_t)k * 128 + n] : 0.0f;
    g_wt[(size_t)(chunk0 + cl) * 4096 + rem] = tf32r(v);
}

// A-fill: per-thread constants hoisted (mtile==wid, kstep==slot j, lane phase fixed).
template <int L0>
__device__ __forceinline__ void fill_A(
    float4* __restrict__ adst, int tid, int icbase, int c,
    const float* __restrict__ xm0, const float* __restrict__ xm1,
    const float* __restrict__ hm0, const float* __restrict__ hm1,
    const uint32_t* __restrict__ lut)
{
    #pragma unroll
    for (int j = 0; j < 4; ++j) {
        int k = icbase + j * 8 + c;
        int f0, g0, f1, g1;
        if (L0) {
            uint32_t u0 = lut[k], u1 = lut[k + 4];
            f0 = u0 & 255; g0 = u0 >> 8;
            f1 = u1 & 255; g1 = u1 >> 8;
        } else {
            f0 = k >> 6; g0 = k & 63;
            f1 = (k + 4) >> 6; g1 = (k + 4) & 63;
        }
        float4 o;
        o.x = tf32r(xm0[f0] * hm0[g0]);
        o.y = tf32r(xm1[f0] * hm1[g0]);
        o.z = tf32r(xm0[f1] * hm0[g1]);
        o.w = tf32r(xm1[f1] * hm1[g1]);
        adst[tid + 256 * j] = o;
    }
}

__device__ __forceinline__ void ldB(uint4* b, const uint4* __restrict__ p) {
    #pragma unroll
    for (int kp = 0; kp < 2; ++kp)
        #pragma unroll
        for (int nt = 0; nt < 4; ++nt)
            b[kp * 4 + nt] = __ldg(p + kp * 512 + nt * 32);
}

__global__ void __launch_bounds__(256, 2) cin_mma_kernel(
    const float* __restrict__ x,
    const float* __restrict__ b0, const float* __restrict__ b1,
    const float* __restrict__ b2,
    float* __restrict__ out)
{
    extern __shared__ char smem[];
    float*    osum   = (float*)(smem + SM_OSUM);
    float*    bias_s = (float*)(smem + SM_BIAS);
    uint32_t* lut    = (uint32_t*)(smem + SM_LUT);
    float*    xs     = (float*)(smem + SM_XS);   // [m][41]
    float*    hs     = (float*)(smem + SM_HS);   // [m][65]

    const int tid = threadIdx.x, lane = tid & 31, wid = tid >> 5;
    const int pair0 = blockIdx.x * 128;
    const int wm = wid & 1, wn = wid >> 1;
    const int c = lane & 3;
    const int m = wid * 16 + (lane >> 2);        // fill rows: m, m+8

    for (int i = tid; i < 2048; i += 256) osum[i] = 0.0f;
    for (int i = tid; i < 128 * 39; i += 256) {
        int mm = i & 127, f = i >> 7, pr = pair0 + mm;
        xs[mm * 41 + f] = x[((size_t)(pr >> 4) * 39 + f) * 16 + (pr & 15)];
    }
    for (int i = tid; i < 384; i += 256) {
        const float* bp = (i < 128) ? b0 : ((i < 256) ? b1 : b2);
        bias_s[i] = bp[i & 127];
    }
    for (int k = tid; k < 800; k += 256) {
        int f = 0, s = 0, g = 0;
        if (k < 780) {
            while (s + (39 - f) <= k) { s += 39 - f; ++f; }
            g = f + (k - s);
        } else f = 0;
        lut[k] = (uint32_t)f | ((uint32_t)g << 8);
    }

    float acc[4][4][4];
    #pragma unroll
    for (int a = 0; a < 4; ++a)
        #pragma unroll
        for (int b = 0; b < 4; ++b)
            #pragma unroll
            for (int cc = 0; cc < 4; ++cc) acc[a][b][cc] = 0.0f;

    float4* a0 = (float4*)(smem + SM_A0);
    float4* a1 = (float4*)(smem + SM_A1);
    const uint4* bptr = (const uint4*)g_wt + (wn * 128 + lane);
    uint4 bcur[8];
    ldB(bcur, bptr);                              // prefetch chunk 0
    int pb = 0;

    const float* xm0 = xs + m * 41;
    const float* xm1 = xs + (m + 8) * 41;

    for (int layer = 0; layer < 3; ++layer) {
        const int nck = (layer == 0) ? NCH0 : NCH12;
        const float* hb = (layer == 0) ? xs : hs;
        const int hst = (layer == 0) ? 41 : 65;
        const float* hm0 = hb + m * hst;
        const float* hm1 = hb + (m + 8) * hst;

        __syncthreads();                          // hs/lut/xs writes visible
        if (layer == 0) fill_A<1>(pb ? a1 : a0, tid, 0, c, xm0, xm1, hm0, hm1, lut);
        else            fill_A<0>(pb ? a1 : a0, tid, 0, c, xm0, xm1, hm0, hm1, lut);

        for (int ic = 0; ic < nck; ++ic) {
            __syncthreads();                      // fill(ic) visible; abuf[pb^1] free

            // ---- MMA(ic): A from abuf[pb], B from registers ----
            const uint4* ap = (pb ? (const uint4*)a1 : (const uint4*)a0) + (wm * 128 + lane);
            #pragma unroll
            for (int kp = 0; kp < 2; ++kp) {
                #pragma unroll
                for (int k2 = 0; k2 < 2; ++k2) {
                    int ks = kp * 2 + k2;
                    uint32_t afr[4][4];
                    #pragma unroll
                    for (int mt = 0; mt < 4; ++mt) {
                        uint4 av = ap[ks * 256 + mt * 32];
                        afr[mt][0] = av.x; afr[mt][1] = av.y;
                        afr[mt][2] = av.z; afr[mt][3] = av.w;
                    }
                    #pragma unroll
                    for (int mt = 0; mt < 4; ++mt)
                        #pragma unroll
                        for (int nt = 0; nt < 4; ++nt)
                            mma8(acc[mt][nt], afr[mt],
                                 k2 ? bcur[kp * 4 + nt].z : bcur[kp * 4 + nt].x,
                                 k2 ? bcur[kp * 4 + nt].w : bcur[kp * 4 + nt].y);
                }
            }

            // ---- prefetch B for next chunk (pad chunk at the very end) ----
            bptr += 1024;
            ldB(bcur, bptr);

            // ---- fill(ic+1) into the other buffer ----
            if (ic + 1 < nck) {
                if (layer == 0) fill_A<1>(pb ? a0 : a1, tid, (ic + 1) * 32, c, xm0, xm1, hm0, hm1, lut);
                else            fill_A<0>(pb ? a0 : a1, tid, (ic + 1) * 32, c, xm0, xm1, hm0, hm1, lut);
            }
            pb ^= 1;
        }

        // ---- epilogue: bias + relu, h for next layer, d-sum into osum ----
        #pragma unroll
        for (int mt = 0; mt < 4; ++mt) {
            int b_loc = wm * 4 + mt;
            int me = wm * 64 + mt * 16 + (lane >> 2);
            #pragma unroll
            for (int nt = 0; nt < 4; ++nt) {
                int n = wn * 32 + nt * 8 + (lane & 3) * 2;
                float bi0 = bias_s[layer * 128 + n];
                float bi1 = bias_s[layer * 128 + n + 1];
                float v0 = fmaxf(acc[mt][nt][0] + bi0, 0.0f);
                float v1 = fmaxf(acc[mt][nt][1] + bi1, 0.0f);
                float v2 = fmaxf(acc[mt][nt][2] + bi0, 0.0f);
                float v3 = fmaxf(acc[mt][nt][3] + bi1, 0.0f);
                acc[mt][nt][0] = 0.0f; acc[mt][nt][1] = 0.0f;
                acc[mt][nt][2] = 0.0f; acc[mt][nt][3] = 0.0f;
                if (layer < 2 && n < 64) {
                    hs[me * 65 + n] = v0;       hs[me * 65 + n + 1] = v1;
                    hs[(me + 8) * 65 + n] = v2; hs[(me + 8) * 65 + n + 1] = v3;
                }
                int ch = (layer == 0) ? (n >= 64 ? n - 64 : -1)
                       : (layer == 1) ? (n >= 64 ? n : -1)
                       : (128 + n);
                if (ch >= 0) {
                    atomicAdd(&osum[b_loc * 256 + ch],     v0 + v2);
                    atomicAdd(&osum[b_loc * 256 + ch + 1], v1 + v3);
                }
            }
        }
    }

    __syncthreads();
    const int bbase = blockIdx.x * 8;
    for (int i = tid; i < 2048; i += 256)
        out[(size_t)(bbase + (i >> 8)) * 256 + (i & 255)] = osum[i];
}

extern "C" void kernel_launch(void* const* d_in, const int* in_sizes, int n_in,
                              void* d_out, int out_size) {
    const float* x  = (const float*)d_in[0];
    const float* W0 = (const float*)d_in[1];
    const float* W1 = (const float*)d_in[2];
    const float* W2 = (const float*)d_in[3];
    const float* b0 = (const float*)d_in[4];
    const float* b1 = (const float*)d_in[5];
    const float* b2 = (const float*)d_in[6];
    float* out = (float*)d_out;

    wt_prep0<<<NCH0 * 16, 256>>>(W0);
    wt_prep<<<NCH12 * 16, 256>>>(W1, 2496, NCH0, NCH12);
    wt_prep<<<NCH12 * 16, 256>>>(W2, 2496, NCH0 + NCH12, NCH12);

    cudaFuncSetAttribute(cin_mma_kernel, cudaFuncAttributeMaxDynamicSharedMemorySize, SM_TOT);
    cin_mma_kernel<<<256, 256, SM_TOT>>>(x, b0, b1, b2, out);
}

// round 8
// speedup vs baseline: 6.0449x; 1.0283x over previous
#include <cuda_runtime.h>
#include <cstdint>

// CIN forward via warp-level TF32 mma.sync (m16n8k8), 3 fused GEMM layers.
// Layer 0 symmetric-folded (K0=780, pad 800). B frags in registers, prefetched
// one chunk ahead. A double-buffered in smem, filled with packed f32x2 math:
// LDS.64 row-pairs -> mul.rn.f32x2 -> +magic (exact tf32 rna) -> STS.128.

#define NCH0 25
#define NCH12 78
#define NCHT 181

__device__ __align__(16) float g_wt[(size_t)(NCHT + 1) * 4096];

#define SM_OSUM 0        // 2048 f
#define SM_BIAS 8192     // 384 f
#define SM_LUT  9728     // 800 u32 -> ends 12928
#define SM_XS   12928    // 39*65 float2 = 20280 -> ends 33208 (pad to 33216)
#define SM_HS   33216    // 64*65 float2 = 33280 -> ends 66496 (pad to 66560)
#define SM_A0   66560    // 16 KB
#define SM_A1   82944    // 16 KB
#define SM_TOT  99328

#define MAGIC 0x0000100000001000ULL

__device__ __forceinline__ float tf32r(float v) {
    uint32_t r; asm("cvt.rna.tf32.f32 %0, %1;" : "=r"(r) : "f"(v));
    return __uint_as_float(r);
}
__device__ __forceinline__ unsigned long long mul2(float2 a, float2 b) {
    unsigned long long ua, ub, r;
    asm("mov.b64 %0, {%1, %2};" : "=l"(ua) : "f"(a.x), "f"(a.y));
    asm("mov.b64 %0, {%1, %2};" : "=l"(ub) : "f"(b.x), "f"(b.y));
    asm("mul.rn.f32x2 %0, %1, %2;" : "=l"(r) : "l"(ua), "l"(ub));
    return r;
}
__device__ __forceinline__ void mma8(float* c, const uint32_t* a, uint32_t b0, uint32_t b1) {
    asm volatile("mma.sync.aligned.m16n8k8.row.col.f32.tf32.tf32.f32 "
        "{%0,%1,%2,%3}, {%4,%5,%6,%7}, {%8,%9}, {%0,%1,%2,%3};"
        : "+f"(c[0]), "+f"(c[1]), "+f"(c[2]), "+f"(c[3])
        : "r"(a[0]), "r"(a[1]), "r"(a[2]), "r"(a[3]), "r"(b0), "r"(b1));
}

// ---- W prep (B side, rna-rounded offline). Fragment order:
// rem = ((kp*16+ntile)*32+lane)*4 + r ; ks = kp*2+(r>>1), reg = r&1
// n = ntile*8 + lane/4 ; k = cl*32 + ks*8 + lane%4 + reg*4
__global__ void wt_prep0(const float* __restrict__ W) {   // layer 0, symmetric fold
    int idx = blockIdx.x * 256 + threadIdx.x;
    if (idx >= NCH0 * 4096) return;
    int cl = idx >> 12, rem = idx & 4095;
    int r = rem & 3, lane = (rem >> 2) & 31, ntile = (rem >> 7) & 15, kp = rem >> 11;
    int ks = kp * 2 + (r >> 1), reg = r & 1;
    int n = ntile * 8 + (lane >> 2);
    int k = cl * 32 + ks * 8 + (lane & 3) + reg * 4;
    float v = 0.0f;
    if (k < 780) {
        int f = 0, s = 0;
        while (s + (39 - f) <= k) { s += 39 - f; ++f; }
        int g = f + (k - s);
        v = W[(size_t)(f * 39 + g) * 128 + n];
        if (g != f) v += W[(size_t)(g * 39 + f) * 128 + n];
    }
    g_wt[(size_t)cl * 4096 + rem] = tf32r(v);
}
__global__ void wt_prep(const float* __restrict__ W, int K, int chunk0, int nchunks) {
    int idx = blockIdx.x * 256 + threadIdx.x;
    if (idx >= nchunks * 4096) return;
    int cl = idx >> 12, rem = idx & 4095;
    int r = rem & 3, lane = (rem >> 2) & 31, ntile = (rem >> 7) & 15, kp = rem >> 11;
    int ks = kp * 2 + (r >> 1), reg = r & 1;
    int n = ntile * 8 + (lane >> 2);
    int k = cl * 32 + ks * 8 + (lane & 3) + reg * 4;
    float v = (k < K) ? W[(size_t)k * 128 + n] : 0.0f;
    g_wt[(size_t)(chunk0 + cl) * 4096 + rem] = tf32r(v);
}

// A fill: xrow/hrow point at this thread's (wid*8 + r) float2 column; row
// stride 65 float2. One slot -> one STS.128 of two rna-rounded f32x2 products.
template <int L0>
__device__ __forceinline__ void fill_A(
    ulonglong2* __restrict__ adst, int tid, int icbase, int c,
    const float2* __restrict__ xrow, const float2* __restrict__ hrow,
    const uint32_t* __restrict__ lut)
{
    #pragma unroll
    for (int j = 0; j < 4; ++j) {
        int k = icbase + j * 8 + c;
        int f0, g0, f1, g1;
        if (L0) {
            uint32_t u0 = lut[k], u1 = lut[k + 4];
            f0 = u0 & 255; g0 = u0 >> 8;
            f1 = u1 & 255; g1 = u1 >> 8;
        } else {
            f0 = k >> 6; g0 = k & 63;
            f1 = (k + 4) >> 6; g1 = (k + 4) & 63;
        }
        unsigned long long p0 = mul2(xrow[f0 * 65], hrow[g0 * 65]) + MAGIC;
        unsigned long long p1 = mul2(xrow[f1 * 65], hrow[g1 * 65]) + MAGIC;
        ulonglong2 o; o.x = p0; o.y = p1;
        adst[tid + 256 * j] = o;
    }
}

__device__ __forceinline__ void ldB(uint4* b, const uint4* __restrict__ p) {
    #pragma unroll
    for (int kp = 0; kp < 2; ++kp)
        #pragma unroll
        for (int nt = 0; nt < 4; ++nt)
            b[kp * 4 + nt] = __ldg(p + kp * 512 + nt * 32);
}

__global__ void __launch_bounds__(256, 2) cin_mma_kernel(
    const float* __restrict__ x,
    const float* __restrict__ b0, const float* __restrict__ b1,
    const float* __restrict__ b2,
    float* __restrict__ out)
{
    extern __shared__ char smem[];
    float*    osum   = (float*)(smem + SM_OSUM);
    float*    bias_s = (float*)(smem + SM_BIAS);
    uint32_t* lut    = (uint32_t*)(smem + SM_LUT);
    float2*   xs2    = (float2*)(smem + SM_XS);   // [f][wid*8+r], stride 65
    float2*   hs2    = (float2*)(smem + SM_HS);   // [g][wid*8+r], stride 65

    const int tid = threadIdx.x, lane = tid & 31, wid = tid >> 5;
    const int pair0 = blockIdx.x * 128;
    const int wm = wid & 1, wn = wid >> 1;
    const int c = lane & 3;
    const int colid = wid * 8 + (lane >> 2);      // this thread's (m, m+8) column

    for (int i = tid; i < 2048; i += 256) osum[i] = 0.0f;
    // xs2[f][col].comp = x[b, f, d]: m = (col>>3)*16 + (col&7) + comp*8
    for (int i = tid; i < 128 * 39; i += 256) {
        int m = i & 127, f = i >> 7, pr = pair0 + m;
        float v = x[((size_t)(pr >> 4) * 39 + f) * 16 + (pr & 15)];
        ((float*)xs2)[(f * 65 + (m >> 4) * 8 + (m & 7)) * 2 + ((m >> 3) & 1)] = v;
    }
    for (int i = tid; i < 384; i += 256) {
        const float* bp = (i < 128) ? b0 : ((i < 256) ? b1 : b2);
        bias_s[i] = bp[i & 127];
    }
    for (int k = tid; k < 800; k += 256) {
        int f = 0, s = 0, g = 0;
        if (k < 780) {
            while (s + (39 - f) <= k) { s += 39 - f; ++f; }
            g = f + (k - s);
        } else f = 0;
        lut[k] = (uint32_t)f | ((uint32_t)g << 8);
    }

    float acc[4][4][4];
    #pragma unroll
    for (int a = 0; a < 4; ++a)
        #pragma unroll
        for (int b = 0; b < 4; ++b)
            #pragma unroll
            for (int cc = 0; cc < 4; ++cc) acc[a][b][cc] = 0.0f;

    ulonglong2* a0 = (ulonglong2*)(smem + SM_A0);
    ulonglong2* a1 = (ulonglong2*)(smem + SM_A1);
    const uint4* bptr = (const uint4*)g_wt + (wn * 128 + lane);
    uint4 bcur[8];
    ldB(bcur, bptr);
    int pb = 0;

    const float2* xrow = xs2 + colid;

    for (int layer = 0; layer < 3; ++layer) {
        const int nck = (layer == 0) ? NCH0 : NCH12;
        const float2* hrow = ((layer == 0) ? xs2 : hs2) + colid;

        __syncthreads();                          // xs2/hs2/lut writes visible
        if (layer == 0) fill_A<1>(pb ? a1 : a0, tid, 0, c, xrow, hrow, lut);
        else            fill_A<0>(pb ? a1 : a0, tid, 0, c, xrow, hrow, lut);

        for (int ic = 0; ic < nck; ++ic) {
            __syncthreads();                      // fill(ic) visible; abuf[pb^1] free

            const uint4* ap = (pb ? (const uint4*)a1 : (const uint4*)a0) + (wm * 128 + lane);
            #pragma unroll
            for (int kp = 0; kp < 2; ++kp) {
                #pragma unroll
                for (int k2 = 0; k2 < 2; ++k2) {
                    int ks = kp * 2 + k2;
                    uint32_t afr[4][4];
                    #pragma unroll
                    for (int mt = 0; mt < 4; ++mt) {
                        uint4 av = ap[ks * 256 + mt * 32];
                        afr[mt][0] = av.x; afr[mt][1] = av.y;
                        afr[mt][2] = av.z; afr[mt][3] = av.w;
                    }
                    #pragma unroll
                    for (int mt = 0; mt < 4; ++mt)
                        #pragma unroll
                        for (int nt = 0; nt < 4; ++nt)
                            mma8(acc[mt][nt], afr[mt],
                                 k2 ? bcur[kp * 4 + nt].z : bcur[kp * 4 + nt].x,
                                 k2 ? bcur[kp * 4 + nt].w : bcur[kp * 4 + nt].y);
                }
            }

            bptr += 1024;
            ldB(bcur, bptr);                      // prefetch next chunk's B

            if (ic + 1 < nck) {
                if (layer == 0) fill_A<1>(pb ? a0 : a1, tid, (ic + 1) * 32, c, xrow, hrow, lut);
                else            fill_A<0>(pb ? a0 : a1, tid, (ic + 1) * 32, c, xrow, hrow, lut);
            }
            pb ^= 1;
        }

        // ---- epilogue: bias + relu, h(float2 pairs) for next layer, d-sum ----
        #pragma unroll
        for (int mt = 0; mt < 4; ++mt) {
            int b_loc = wm * 4 + mt;
            int hcol = (wm * 4 + mt) * 8 + (lane >> 2);
            #pragma unroll
            for (int nt = 0; nt < 4; ++nt) {
                int n = wn * 32 + nt * 8 + (lane & 3) * 2;
                float bi0 = bias_s[layer * 128 + n];
                float bi1 = bias_s[layer * 128 + n + 1];
                float v0 = fmaxf(acc[mt][nt][0] + bi0, 0.0f);
                float v1 = fmaxf(acc[mt][nt][1] + bi1, 0.0f);
                float v2 = fmaxf(acc[mt][nt][2] + bi0, 0.0f);
                float v3 = fmaxf(acc[mt][nt][3] + bi1, 0.0f);
                acc[mt][nt][0] = 0.0f; acc[mt][nt][1] = 0.0f;
                acc[mt][nt][2] = 0.0f; acc[mt][nt][3] = 0.0f;
                if (layer < 2 && n < 64) {
                    hs2[n * 65 + hcol]       = make_float2(v0, v2);
                    hs2[(n + 1) * 65 + hcol] = make_float2(v1, v3);
                }
                int ch = (layer == 0) ? (n >= 64 ? n - 64 : -1)
                       : (layer == 1) ? (n >= 64 ? n : -1)
                       : (128 + n);
                if (ch >= 0) {
                    atomicAdd(&osum[b_loc * 256 + ch],     v0 + v2);
                    atomicAdd(&osum[b_loc * 256 + ch + 1], v1 + v3);
                }
            }
        }
    }

    __syncthreads();
    const int bbase = blockIdx.x * 8;
    for (int i = tid; i < 2048; i += 256)
        out[(size_t)(bbase + (i >> 8)) * 256 + (i & 255)] = osum[i];
}

extern "C" void kernel_launch(void* const* d_in, const int* in_sizes, int n_in,
                              void* d_out, int out_size) {
    const float* x  = (const float*)d_in[0];
    const float* W0 = (const float*)d_in[1];
    const float* W1 = (const float*)d_in[2];
    const float* W2 = (const float*)d_in[3];
    const float* b0 = (const float*)d_in[4];
    const float* b1 = (const float*)d_in[5];
    const float* b2 = (const float*)d_in[6];
    float* out = (float*)d_out;

    wt_prep0<<<NCH0 * 16, 256>>>(W0);
    wt_prep<<<NCH12 * 16, 256>>>(W1, 2496, NCH0, NCH12);
    wt_prep<<<NCH12 * 16, 256>>>(W2, 2496, NCH0 + NCH12, NCH12);

    cudaFuncSetAttribute(cin_mma_kernel, cudaFuncAttributeMaxDynamicSharedMemorySize, SM_TOT);
    cin_mma_kernel<<<256, 256, SM_TOT>>>(x, b0, b1, b2, out);
}